// round 13
// baseline (speedup 1.0000x reference)
#include <cuda_runtime.h>
#include <cuda_fp16.h>
#include <cstdint>

#define WTE (15 * 64 * 4096)

// fp16 W tiles [p][a][c][b], pre-scaled by 1024 (epilogue multiplies by 2^-10)
__device__ __align__(16) __half g_Wf[WTE];

// group of each path: 0 -> Lout0, 1 -> Lout1, 2 -> Lout2
__constant__ int c_grp[15] = {0,1,2,1,2,0,1,1,2,2,1,2,2,0,1};

__global__ void prep_w(const float* __restrict__ w) {
    int d = blockIdx.x * 256 + threadIdx.x;
    if (d >= WTE) return;
    int p = d >> 18, a = (d >> 12) & 63, c = (d >> 6) & 63, b = d & 63;
    float f = w[(p << 18) | (c << 12) | (a << 6) | b];
    g_Wf[d] = __float2half(f * 1024.0f);
}

// ---------- smem byte layout (1 CTA, 1024 threads) ----------
// x1: 14*833*4 = 46648 -> [0, 46656)
// x2T: [46656, 93696)  (14*840*4 = 47040)
// P: 2 stages * 18432 -> [93696, 130560)
// W: 3 slots * 9216   -> [130560, 158208)
#define X2_OFF   46656
#define P_OFF    93696
#define P_STRIDE 18432
#define W_OFF    130560
#define W_STRIDE 9216
#define SMEM_TOT 158208
#define NTHR     1024

__device__ __forceinline__ uint32_t smem_u32(const void* p) {
    uint32_t a;
    asm("{ .reg .u64 t; cvta.to.shared.u64 t, %1; cvt.u32.u64 %0, t; }" : "=r"(a) : "l"(p));
    return a;
}

#define LDSM4(r, addr) asm volatile( \
    "ldmatrix.sync.aligned.m8n8.x4.shared.b16 {%0,%1,%2,%3}, [%4];" \
    : "=r"((r)[0]), "=r"((r)[1]), "=r"((r)[2]), "=r"((r)[3]) : "r"(addr))

#define MMAF(d, a, bb0, bb1) asm volatile( \
    "mma.sync.aligned.m16n8k16.row.col.f32.f16.f16.f32 " \
    "{%0,%1,%2,%3}, {%4,%5,%6,%7}, {%8,%9}, {%0,%1,%2,%3};" \
    : "+f"((d)[0]), "+f"((d)[1]), "+f"((d)[2]), "+f"((d)[3]) \
    : "r"((a)[0]), "r"((a)[1]), "r"((a)[2]), "r"((a)[3]), "r"(bb0), "r"(bb1))

// one m-frag (16 rows) x NF n16-frags, single fp16 pass, K=64 (4 k-steps)
template<int NF>
__device__ __forceinline__ void warp_mma(float (*acc)[4], int m0, int n0,
                                         uint32_t pP, uint32_t pW, int lane) {
    const uint32_t aoff = (uint32_t)((lane & 15) * 144 + ((lane >> 4) << 4));
    const uint32_t boff = (uint32_t)(((lane & 7) + ((lane >> 4) & 1) * 8) * 144 + (lane & 8) * 2);
#pragma unroll
    for (int ks = 0; ks < 4; ks++) {
        const uint32_t kb = ks * 32;
        uint32_t ah[4];
        LDSM4(ah, pP + (uint32_t)(m0 * 144) + kb + aoff);
        uint32_t bh[NF][4];
#pragma unroll
        for (int nj = 0; nj < NF; nj++)
            LDSM4(bh[nj], pW + (uint32_t)((n0 + nj * 16) * 144) + kb + boff);
#pragma unroll
        for (int nj = 0; nj < NF; nj++)
#pragma unroll
            for (int s = 0; s < 2; s++)
                MMAF(acc[nj * 2 + s], ah, bh[nj][s * 2], bh[nj][s * 2 + 1]);
    }
}

// first 512 threads issue the whole 9KB W tile (512 x 16B) via cp.async
__device__ __forceinline__ void prefetch_w(int p, int a, int slot, uint32_t sb, int tid) {
    if (tid >= 512) return;
    const size_t tile = ((size_t)(p * 64 + a)) << 12;
    int cR = tid >> 3, seg = tid & 7;
    const __half* src = g_Wf + tile + cR * 64 + seg * 8;
    uint32_t dst = sb + W_OFF + slot * W_STRIDE + cR * 144 + seg * 16;
    asm volatile("cp.async.cg.shared.global [%0], [%1], 16;" :: "r"(dst), "l"(src));
}

#define G8(nm, off) float nm[8]; { const float4* q_ = (const float4*)(bz + (off) + b0); \
    float4 t0_ = q_[0], t1_ = q_[1]; nm[0]=t0_.x; nm[1]=t0_.y; nm[2]=t0_.z; nm[3]=t0_.w; \
    nm[4]=t1_.x; nm[5]=t1_.y; nm[6]=t1_.z; nm[7]=t1_.w; }

__device__ __forceinline__ void gen_chunk(int p, int g, int a, int nzv,
                                          const float* smemf, char* smemc,
                                          uint32_t pdst, int tid) {
    const int tasks = (g == 2) ? 1024 : (g == 1 ? 384 : 128);
    for (int t = tid; t < tasks; t += NTHR) {
        const int row = t >> 3;
        const int b0 = (t & 7) << 3;
        int z, u;
        if (g == 2)      { z = row / 9; u = row - z * 9; }
        else if (g == 1) { z = row / 3; u = row - z * 3; }
        else             { z = row;     u = 0; }
        if (z > nzv - 1) z = nzv - 1;
        const float* ax = smemf + z * 833;
        const float* bz = smemf + 11664 + z * 840;
        float v[8];
        switch (p) {
        case 0: { G8(s, 0); float A = ax[a];
#pragma unroll
            for (int j = 0; j < 8; j++) v[j] = A * s[j]; } break;
        case 1: { G8(s, 64 + u * 64); float A = ax[a];
#pragma unroll
            for (int j = 0; j < 8; j++) v[j] = A * s[j]; } break;
        case 2: { G8(s, 256 + u * 64); float A = ax[a];
#pragma unroll
            for (int j = 0; j < 8; j++) v[j] = A * s[j]; } break;
        case 3: { G8(s, 0); float A = ax[64 + 3 * a + u];
#pragma unroll
            for (int j = 0; j < 8; j++) v[j] = A * s[j]; } break;
        case 4: { G8(s, 64 + (u % 3) * 64); float A = ax[64 + 3 * a + u / 3];
#pragma unroll
            for (int j = 0; j < 8; j++) v[j] = A * s[j]; } break;
        case 5: { G8(q0, 64); G8(q1, 128); G8(q2, 192);
            const float* av = ax + 64 + 3 * a;
#pragma unroll
            for (int j = 0; j < 8; j++)
                v[j] = fmaf(av[2], q2[j], fmaf(av[1], q1[j], av[0] * q0[j])); } break;
        case 6: { int u1 = (u + 1) % 3, u2 = (u + 2) % 3;
            G8(qa, 64 + u2 * 64); G8(qb, 64 + u1 * 64);
            const float* av = ax + 64 + 3 * a;
#pragma unroll
            for (int j = 0; j < 8; j++) v[j] = av[u1] * qa[j] - av[u2] * qb[j]; } break;
        case 7: { G8(q0, 256 + (3 * u) * 64); G8(q1, 256 + (3 * u + 1) * 64); G8(q2, 256 + (3 * u + 2) * 64);
            const float* av = ax + 64 + 3 * a;
#pragma unroll
            for (int j = 0; j < 8; j++)
                v[j] = fmaf(av[2], q2[j], fmaf(av[1], q1[j], av[0] * q0[j])); } break;
        case 8: { int e = u / 3, gg = u % 3, g1 = (gg + 1) % 3, g2 = (gg + 2) % 3;
            G8(qa, 256 + (3 * e + g2) * 64); G8(qb, 256 + (3 * e + g1) * 64);
            const float* av = ax + 64 + 3 * a;
#pragma unroll
            for (int j = 0; j < 8; j++) v[j] = av[g1] * qa[j] - av[g2] * qb[j]; } break;
        case 9: { G8(s, 0); float A = ax[256 + 9 * a + u];
#pragma unroll
            for (int j = 0; j < 8; j++) v[j] = A * s[j]; } break;
        case 10: { G8(q0, 64); G8(q1, 128); G8(q2, 192);
            const float* m = ax + 256 + 9 * a + 3 * u;
#pragma unroll
            for (int j = 0; j < 8; j++)
                v[j] = fmaf(m[2], q2[j], fmaf(m[1], q1[j], m[0] * q0[j])); } break;
        case 11: { int d = u / 3, gg = u % 3, g1 = (gg + 1) % 3, g2 = (gg + 2) % 3;
            G8(qa, 64 + g2 * 64); G8(qb, 64 + g1 * 64);
            const float* m = ax + 256 + 9 * a + 3 * d;
#pragma unroll
            for (int j = 0; j < 8; j++) v[j] = m[g1] * qa[j] - m[g2] * qb[j]; } break;
        case 12: { int d = u / 3, f = u % 3;
            const float* m = ax + 256 + 9 * a + 3 * d;
            G8(q0, 256 + (3 * f) * 64); G8(q1, 256 + (3 * f + 1) * 64); G8(q2, 256 + (3 * f + 2) * 64);
#pragma unroll
            for (int j = 0; j < 8; j++)
                v[j] = fmaf(m[2], q2[j], fmaf(m[1], q1[j], m[0] * q0[j])); } break;
        case 13: { const float* m = ax + 256 + 9 * a;
#pragma unroll
            for (int j = 0; j < 8; j++) v[j] = 0.f;
#pragma unroll
            for (int t2 = 0; t2 < 9; t2++) {
                const float4* q_ = (const float4*)(bz + 256 + t2 * 64 + b0);
                float4 a0 = q_[0], a1 = q_[1];
                float mm = m[t2];
                v[0] = fmaf(mm, a0.x, v[0]); v[1] = fmaf(mm, a0.y, v[1]);
                v[2] = fmaf(mm, a0.z, v[2]); v[3] = fmaf(mm, a0.w, v[3]);
                v[4] = fmaf(mm, a1.x, v[4]); v[5] = fmaf(mm, a1.y, v[5]);
                v[6] = fmaf(mm, a1.z, v[6]); v[7] = fmaf(mm, a1.w, v[7]);
            } } break;
        default: { int u1 = (u + 1) % 3, u2 = (u + 2) % 3;   // p14
            const float* m1 = ax + 256 + 9 * a + 3 * u1;
            const float* m2 = ax + 256 + 9 * a + 3 * u2;
#pragma unroll
            for (int j = 0; j < 8; j++) v[j] = 0.f;
#pragma unroll
            for (int i = 0; i < 3; i++) {
                const float4* qa_ = (const float4*)(bz + 256 + (3 * u2 + i) * 64 + b0);
                const float4* qb_ = (const float4*)(bz + 256 + (3 * u1 + i) * 64 + b0);
                float4 a0 = qa_[0], a1 = qa_[1], c0 = qb_[0], c1 = qb_[1];
                float f1 = m1[i], f2 = m2[i];
                v[0] += f1 * a0.x - f2 * c0.x; v[1] += f1 * a0.y - f2 * c0.y;
                v[2] += f1 * a0.z - f2 * c0.z; v[3] += f1 * a0.w - f2 * c0.w;
                v[4] += f1 * a1.x - f2 * c1.x; v[5] += f1 * a1.y - f2 * c1.y;
                v[6] += f1 * a1.z - f2 * c1.z; v[7] += f1 * a1.w - f2 * c1.w;
            } } break;
        }
        uint32_t hp[4];
#pragma unroll
        for (int jj = 0; jj < 4; jj++) {
            __half2 h = __floats2half2_rn(v[2 * jj], v[2 * jj + 1]);
            hp[jj] = *(uint32_t*)&h;
        }
        *(uint4*)(smemc + pdst + row * 144 + b0 * 2) = make_uint4(hp[0], hp[1], hp[2], hp[3]);
    }
}

__global__ void __launch_bounds__(NTHR, 1)
tp_hmma_kernel(const float* __restrict__ x1, const float* __restrict__ x2,
               float* __restrict__ out) {
    extern __shared__ char smem[];
    float* smemf = (float*)smem;
    const int tid = threadIdx.x, w = tid >> 5, lane = tid & 31;
    const int z0 = blockIdx.x * 14;
    const int nzv = min(14, 4096 - z0);
    const uint32_t sb = smem_u32(smem);
    const float SCL = 1.0f / 1024.0f;   // undo the W*1024 prescale

    // stage x1 (natural, stride 833) and x2 (component-major, stride 840)
    for (int i = tid; i < 14 * 832; i += NTHR) {
        int z = i / 832, f = i - z * 832;
        int zg = z0 + z; if (zg > 4095) zg = 4095;
        smemf[z * 833 + f] = x1[(size_t)zg * 832 + f];
        float v2 = x2[(size_t)zg * 832 + f];
        int d;
        if (f < 64) d = f;
        else if (f < 256) { int g = f - 64; d = 64 + (g % 3) * 64 + g / 3; }
        else { int g = f - 256; d = 256 + (g % 9) * 64 + g / 9; }
        smemf[11664 + z * 840 + d] = v2;
    }

    // 32 warps. g2: all warps, m-frag (w&7), n16-frag (w>>3), NF=1 -> acc2[2][4]
    // g1: warps 0-11, m-frag (w%3), n16-slice (w/3), NF=1         -> accX[2][4]
    // g0: warps 12-15, m-frag 0, n16-slice (w-12), NF=1           -> accX[2][4]
    float acc2[2][4], accX[2][4];
#pragma unroll
    for (int ni = 0; ni < 2; ni++)
#pragma unroll
        for (int di = 0; di < 4; di++) {
            acc2[ni][di] = 0.f;
            accX[ni][di] = 0.f;
        }

    // prologue: W0, W1 in flight; gen chunk0; wait W0; publish
    prefetch_w(0, 0, 0, sb, tid);
    asm volatile("cp.async.commit_group;" ::: "memory");
    prefetch_w(0, 1, 1, sb, tid);
    asm volatile("cp.async.commit_group;" ::: "memory");
    __syncthreads();                        // staging visible for gen
    gen_chunk(0, c_grp[0], 0, nzv, smemf, smem, P_OFF, tid);
    asm volatile("cp.async.wait_group 1;" ::: "memory");   // W0 done
    __syncthreads();                        // publish P0 + W0

    // invariant at top of iter c: P[c&1] + W[c] visible to all; W[c+1] in flight
    for (int c = 0; c < 960; c++) {
        const int cn = c + 2;
        if (cn < 960) prefetch_w(cn >> 6, cn & 63, cn % 3, sb, tid);
        asm volatile("cp.async.commit_group;" ::: "memory");
        const int cg = c + 1;
        if (cg < 960)
            gen_chunk(cg >> 6, c_grp[cg >> 6], cg & 63, nzv, smemf, smem,
                      P_OFF + (cg & 1) * P_STRIDE, tid);
        asm volatile("cp.async.wait_group 1;" ::: "memory");   // W[c+1] landed
        const int g = c_grp[c >> 6];
        const uint32_t pP = sb + P_OFF + (c & 1) * P_STRIDE;
        const uint32_t pW = sb + W_OFF + (c % 3) * W_STRIDE;
        if (g == 2) {
            warp_mma<1>(acc2, (w & 7) * 16, (w >> 3) * 16, pP, pW, lane);
        } else if (g == 1) {
            if (w < 12) warp_mma<1>(accX, (w % 3) * 16, (w / 3) * 16, pP, pW, lane);
        } else {
            if (w >= 12 && w < 16) warp_mma<1>(accX, 0, (w - 12) * 16, pP, pW, lane);
        }
        __syncthreads();   // publish P[(c+1)&1] and W[c+1]
    }

    // ---- epilogue (D frag: row=(l>>2)+8*(di>>1), col=2*(l&3)+(di&1)); scale by 2^-10 ----
    {
        const int m0 = (w & 7) * 16, n0 = (w >> 3) * 16;
#pragma unroll
        for (int ni = 0; ni < 2; ni++)
#pragma unroll
            for (int di = 0; di < 4; di++) {
                int row = m0 + (lane >> 2) + (di >> 1) * 8;
                int col = n0 + ni * 8 + (lane & 3) * 2 + (di & 1);
                if (row < 126) {
                    int z = row / 9, u = row - z * 9;
                    if (z < nzv)
                        out[(size_t)(z0 + z) * 832 + 256 + col * 9 + u] = acc2[ni][di] * SCL;
                }
            }
    }
    if (w < 12) {
        const int m0 = (w % 3) * 16, n0 = (w / 3) * 16;
#pragma unroll
        for (int ni = 0; ni < 2; ni++)
#pragma unroll
            for (int di = 0; di < 4; di++) {
                int row = m0 + (lane >> 2) + (di >> 1) * 8;
                int col = n0 + ni * 8 + (lane & 3) * 2 + (di & 1);
                if (row < 42) {
                    int z = row / 3, u = row - z * 3;
                    if (z < nzv)
                        out[(size_t)(z0 + z) * 832 + 64 + col * 3 + u] = accX[ni][di] * SCL;
                }
            }
    } else if (w < 16) {
        const int n0 = (w - 12) * 16;
#pragma unroll
        for (int ni = 0; ni < 2; ni++)
#pragma unroll
            for (int di = 0; di < 4; di++) {
                int row = (lane >> 2) + (di >> 1) * 8;
                int col = n0 + ni * 8 + (lane & 3) * 2 + (di & 1);
                if (row < nzv)
                    out[(size_t)(z0 + row) * 832 + col] = accX[ni][di] * SCL;
            }
    }
}

extern "C" void kernel_launch(void* const* d_in, const int* in_sizes, int n_in,
                              void* d_out, int out_size) {
    const float* x1 = (const float*)d_in[0];
    const float* x2 = (const float*)d_in[1];
    const float* w  = (const float*)d_in[2];
    float* out = (float*)d_out;

    prep_w<<<(WTE + 255) / 256, 256>>>(w);

    static int attr_set = 0;
    if (!attr_set) {
        cudaFuncSetAttribute(tp_hmma_kernel, cudaFuncAttributeMaxDynamicSharedMemorySize, SMEM_TOT);
        attr_set = 1;
    }
    tp_hmma_kernel<<<293, NTHR, SMEM_TOT>>>(x1, x2, out);
}

// round 14
// speedup vs baseline: 1.4988x; 1.4988x over previous
#include <cuda_runtime.h>
#include <cuda_fp16.h>
#include <cstdint>

#define WTE (15 * 64 * 4096)

// fp16 W tiles [p][a][c][b], pre-scaled by 1024 (epilogue multiplies by 2^-10)
__device__ __align__(16) __half g_Wf[WTE];

// group of each path: 0 -> Lout0, 1 -> Lout1, 2 -> Lout2
__constant__ int c_grp[15] = {0,1,2,1,2,0,1,1,2,2,1,2,2,0,1};

__global__ void prep_w(const float* __restrict__ w) {
    int d = blockIdx.x * 256 + threadIdx.x;
    if (d >= WTE) return;
    int p = d >> 18, a = (d >> 12) & 63, c = (d >> 6) & 63, b = d & 63;
    float f = w[(p << 18) | (c << 12) | (a << 6) | b];
    g_Wf[d] = __float2half(f * 1024.0f);
}

// ---------- smem byte layout (1 CTA, 512 threads) ----------
// x1: 14*833*4 = 46648 -> [0, 46656)
// x2T: [46656, 93696)  (14*840*4 = 47040)
// P: 2 stages * 18432 -> [93696, 130560)
// W: 3 slots * 9216   -> [130560, 158208)
#define P_OFF    93696
#define P_STRIDE 18432
#define W_OFF    130560
#define W_STRIDE 9216
#define SMEM_TOT 158208
#define NTHR     512

__device__ __forceinline__ uint32_t smem_u32(const void* p) {
    uint32_t a;
    asm("{ .reg .u64 t; cvta.to.shared.u64 t, %1; cvt.u32.u64 %0, t; }" : "=r"(a) : "l"(p));
    return a;
}

#define LDSM4(r, addr) asm volatile( \
    "ldmatrix.sync.aligned.m8n8.x4.shared.b16 {%0,%1,%2,%3}, [%4];" \
    : "=r"((r)[0]), "=r"((r)[1]), "=r"((r)[2]), "=r"((r)[3]) : "r"(addr))

#define MMAF(d, a, bb0, bb1) asm volatile( \
    "mma.sync.aligned.m16n8k16.row.col.f32.f16.f16.f32 " \
    "{%0,%1,%2,%3}, {%4,%5,%6,%7}, {%8,%9}, {%0,%1,%2,%3};" \
    : "+f"((d)[0]), "+f"((d)[1]), "+f"((d)[2]), "+f"((d)[3]) \
    : "r"((a)[0]), "r"((a)[1]), "r"((a)[2]), "r"((a)[3]), "r"(bb0), "r"(bb1))

// one m-frag (16 rows) x NF n16-frags, single fp16 pass, K=64 (4 k-steps)
template<int NF>
__device__ __forceinline__ void warp_mma(float (*acc)[4], int m0, int n0,
                                         uint32_t pP, uint32_t pW, int lane) {
    const uint32_t aoff = (uint32_t)((lane & 15) * 144 + ((lane >> 4) << 4));
    const uint32_t boff = (uint32_t)(((lane & 7) + ((lane >> 4) & 1) * 8) * 144 + (lane & 8) * 2);
#pragma unroll
    for (int ks = 0; ks < 4; ks++) {
        const uint32_t kb = ks * 32;
        uint32_t ah[4];
        LDSM4(ah, pP + (uint32_t)(m0 * 144) + kb + aoff);
        uint32_t bh[NF][4];
#pragma unroll
        for (int nj = 0; nj < NF; nj++)
            LDSM4(bh[nj], pW + (uint32_t)((n0 + nj * 16) * 144) + kb + boff);
#pragma unroll
        for (int nj = 0; nj < NF; nj++)
#pragma unroll
            for (int s = 0; s < 2; s++)
                MMAF(acc[nj * 2 + s], ah, bh[nj][s * 2], bh[nj][s * 2 + 1]);
    }
}

// 512 threads issue the whole 9KB W tile (512 x 16B) via cp.async
__device__ __forceinline__ void prefetch_w(int p, int a, int slot, uint32_t sb, int tid) {
    const size_t tile = ((size_t)(p * 64 + a)) << 12;
    int cR = tid >> 3, seg = tid & 7;
    const __half* src = g_Wf + tile + cR * 64 + seg * 8;
    uint32_t dst = sb + W_OFF + slot * W_STRIDE + cR * 144 + seg * 16;
    asm volatile("cp.async.cg.shared.global [%0], [%1], 16;" :: "r"(dst), "l"(src));
}

__device__ __forceinline__ float4 f4mul(float s, float4 v) {
    return make_float4(s * v.x, s * v.y, s * v.z, s * v.w);
}
__device__ __forceinline__ float4 f4fma(float s, float4 v, float4 c) {
    return make_float4(fmaf(s, v.x, c.x), fmaf(s, v.y, c.y), fmaf(s, v.z, c.z), fmaf(s, v.w, c.w));
}
__device__ __forceinline__ float4 f4sub2(float s1, float4 a, float s2, float4 b) {
    return make_float4(s1 * a.x - s2 * b.x, s1 * a.y - s2 * b.y,
                       s1 * a.z - s2 * b.z, s1 * a.w - s2 * b.w);
}
__device__ __forceinline__ float4 ld4(const float* p) { return *(const float4*)p; }
__device__ __forceinline__ void st4(char* smemc, uint32_t off, float4 v) {
    __half2 h0 = __floats2half2_rn(v.x, v.y);
    __half2 h1 = __floats2half2_rn(v.z, v.w);
    uint2 u;
    u.x = *(uint32_t*)&h0;
    u.y = *(uint32_t*)&h1;
    *(uint2*)(smemc + off) = u;
}
#define DOT3(r0, r1, r2, m0, m1, m2) f4fma(m2, r2, f4fma(m1, r1, f4mul(m0, r0)))

// u-triple fused P generation. Task = (vrow, b-quad).
__device__ __forceinline__ void gen_chunk(int p, int g, int a, int nzv,
                                          const float* smemf, char* smemc,
                                          uint32_t pdst, int tid) {
    if (g == 2) {
        for (int t = tid; t < 672; t += NTHR) {
            const int vr = t >> 4, b0 = (t & 15) << 2;
            const int zr = vr / 3, j = vr - zr * 3;
            const int z = (zr > nzv - 1) ? nzv - 1 : zr;
            const float* ax = smemf + z * 833;
            const float* bz = smemf + 11664 + z * 840;
            const float* av = ax + 64 + 3 * a;
            const float* am = ax + 256 + 9 * a;
            float4 v0, v1, v2;
            switch (p) {
            case 2: { float A = ax[a];
                v0 = f4mul(A, ld4(bz + 256 + j * 64 + b0));
                v1 = f4mul(A, ld4(bz + 256 + (j + 3) * 64 + b0));
                v2 = f4mul(A, ld4(bz + 256 + (j + 6) * 64 + b0)); } break;
            case 4: { float4 s = ld4(bz + 64 + j * 64 + b0);
                v0 = f4mul(av[0], s); v1 = f4mul(av[1], s); v2 = f4mul(av[2], s); } break;
            case 8: { int g1 = (j + 1) % 3, g2 = (j + 2) % 3;
                float A1 = av[g1], A2 = av[g2];
                v0 = f4sub2(A1, ld4(bz + 256 + g2 * 64 + b0), A2, ld4(bz + 256 + g1 * 64 + b0));
                v1 = f4sub2(A1, ld4(bz + 256 + (3 + g2) * 64 + b0), A2, ld4(bz + 256 + (3 + g1) * 64 + b0));
                v2 = f4sub2(A1, ld4(bz + 256 + (6 + g2) * 64 + b0), A2, ld4(bz + 256 + (6 + g1) * 64 + b0)); } break;
            case 9: { float4 s = ld4(bz + b0);
                v0 = f4mul(am[j], s); v1 = f4mul(am[j + 3], s); v2 = f4mul(am[j + 6], s); } break;
            case 11: { int g1 = (j + 1) % 3, g2 = (j + 2) % 3;
                float4 qa = ld4(bz + 64 + g2 * 64 + b0), qb = ld4(bz + 64 + g1 * 64 + b0);
                v0 = f4sub2(am[g1], qa, am[g2], qb);
                v1 = f4sub2(am[3 + g1], qa, am[3 + g2], qb);
                v2 = f4sub2(am[6 + g1], qa, am[6 + g2], qb); } break;
            default: { // p12, f=j
                float4 q0 = ld4(bz + 256 + (3 * j) * 64 + b0);
                float4 q1 = ld4(bz + 256 + (3 * j + 1) * 64 + b0);
                float4 q2 = ld4(bz + 256 + (3 * j + 2) * 64 + b0);
                v0 = DOT3(q0, q1, q2, am[0], am[1], am[2]);
                v1 = DOT3(q0, q1, q2, am[3], am[4], am[5]);
                v2 = DOT3(q0, q1, q2, am[6], am[7], am[8]); } break;
            }
            const uint32_t base = pdst + (uint32_t)((zr * 9 + j) * 144) + b0 * 2;
            st4(smemc, base, v0);
            st4(smemc, base + 3 * 144, v1);
            st4(smemc, base + 6 * 144, v2);
        }
    } else if (g == 1) {
        for (int t = tid; t < 224; t += NTHR) {
            const int zr = t >> 4, b0 = (t & 15) << 2;
            const int z = (zr > nzv - 1) ? nzv - 1 : zr;
            const float* ax = smemf + z * 833;
            const float* bz = smemf + 11664 + z * 840;
            const float* av = ax + 64 + 3 * a;
            const float* am = ax + 256 + 9 * a;
            float4 v0, v1, v2;
            switch (p) {
            case 1: { float A = ax[a];
                v0 = f4mul(A, ld4(bz + 64 + b0));
                v1 = f4mul(A, ld4(bz + 128 + b0));
                v2 = f4mul(A, ld4(bz + 192 + b0)); } break;
            case 3: { float4 s = ld4(bz + b0);
                v0 = f4mul(av[0], s); v1 = f4mul(av[1], s); v2 = f4mul(av[2], s); } break;
            case 6: { float4 c0 = ld4(bz + 64 + b0), c1 = ld4(bz + 128 + b0), c2 = ld4(bz + 192 + b0);
                v0 = f4sub2(av[1], c2, av[2], c1);
                v1 = f4sub2(av[2], c0, av[0], c2);
                v2 = f4sub2(av[0], c1, av[1], c0); } break;
            case 7: {
                v0 = DOT3(ld4(bz + 256 + b0), ld4(bz + 256 + 64 + b0), ld4(bz + 256 + 128 + b0),
                          av[0], av[1], av[2]);
                v1 = DOT3(ld4(bz + 256 + 192 + b0), ld4(bz + 256 + 256 + b0), ld4(bz + 256 + 320 + b0),
                          av[0], av[1], av[2]);
                v2 = DOT3(ld4(bz + 256 + 384 + b0), ld4(bz + 256 + 448 + b0), ld4(bz + 256 + 512 + b0),
                          av[0], av[1], av[2]); } break;
            case 10: { float4 c0 = ld4(bz + 64 + b0), c1 = ld4(bz + 128 + b0), c2 = ld4(bz + 192 + b0);
                v0 = DOT3(c0, c1, c2, am[0], am[1], am[2]);
                v1 = DOT3(c0, c1, c2, am[3], am[4], am[5]);
                v2 = DOT3(c0, c1, c2, am[6], am[7], am[8]); } break;
            default: { // p14
                v0 = make_float4(0.f, 0.f, 0.f, 0.f); v1 = v0; v2 = v0;
#pragma unroll
                for (int i = 0; i < 3; i++) {
                    float4 r0 = ld4(bz + 256 + i * 64 + b0);
                    float4 r3 = ld4(bz + 256 + (3 + i) * 64 + b0);
                    float4 r6 = ld4(bz + 256 + (6 + i) * 64 + b0);
                    v0.x += am[3+i]*r6.x - am[6+i]*r3.x; v0.y += am[3+i]*r6.y - am[6+i]*r3.y;
                    v0.z += am[3+i]*r6.z - am[6+i]*r3.z; v0.w += am[3+i]*r6.w - am[6+i]*r3.w;
                    v1.x += am[6+i]*r0.x - am[i]*r6.x;   v1.y += am[6+i]*r0.y - am[i]*r6.y;
                    v1.z += am[6+i]*r0.z - am[i]*r6.z;   v1.w += am[6+i]*r0.w - am[i]*r6.w;
                    v2.x += am[i]*r3.x - am[3+i]*r0.x;   v2.y += am[i]*r3.y - am[3+i]*r0.y;
                    v2.z += am[i]*r3.z - am[3+i]*r0.z;   v2.w += am[i]*r3.w - am[3+i]*r0.w;
                } } break;
            }
            const uint32_t base = pdst + (uint32_t)((zr * 3) * 144) + b0 * 2;
            st4(smemc, base, v0);
            st4(smemc, base + 144, v1);
            st4(smemc, base + 288, v2);
        }
    } else {
        for (int t = tid; t < 224; t += NTHR) {
            const int zr = t >> 4, b0 = (t & 15) << 2;
            const int z = (zr > nzv - 1) ? nzv - 1 : zr;
            const float* ax = smemf + z * 833;
            const float* bz = smemf + 11664 + z * 840;
            const float* av = ax + 64 + 3 * a;
            const float* am = ax + 256 + 9 * a;
            float4 v0;
            switch (p) {
            case 0: v0 = f4mul(ax[a], ld4(bz + b0)); break;
            case 5: v0 = DOT3(ld4(bz + 64 + b0), ld4(bz + 128 + b0), ld4(bz + 192 + b0),
                              av[0], av[1], av[2]); break;
            default: { // p13
                v0 = make_float4(0.f, 0.f, 0.f, 0.f);
#pragma unroll
                for (int t2 = 0; t2 < 9; t2++)
                    v0 = f4fma(am[t2], ld4(bz + 256 + t2 * 64 + b0), v0);
            } break;
            }
            st4(smemc, pdst + (uint32_t)(zr * 144) + b0 * 2, v0);
        }
    }
}

__global__ void __launch_bounds__(NTHR, 1)
tp_hmma_kernel(const float* __restrict__ x1, const float* __restrict__ x2,
               float* __restrict__ out) {
    extern __shared__ char smem[];
    float* smemf = (float*)smem;
    const int tid = threadIdx.x, w = tid >> 5, lane = tid & 31;
    const int z0 = blockIdx.x * 14;
    const int nzv = min(14, 4096 - z0);
    const uint32_t sb = smem_u32(smem);
    const float SCL = 1.0f / 1024.0f;   // undo the W*1024 prescale

    // stage x1 (natural, stride 833) and x2 (component-major, stride 840)
    for (int i = tid; i < 14 * 832; i += NTHR) {
        int z = i / 832, f = i - z * 832;
        int zg = z0 + z; if (zg > 4095) zg = 4095;
        smemf[z * 833 + f] = x1[(size_t)zg * 832 + f];
        float v2 = x2[(size_t)zg * 832 + f];
        int d;
        if (f < 64) d = f;
        else if (f < 256) { int g = f - 64; d = 64 + (g % 3) * 64 + g / 3; }
        else { int g = f - 256; d = 256 + (g % 9) * 64 + g / 9; }
        smemf[11664 + z * 840 + d] = v2;
    }

    // 16 warps. g2: all warps, m-frag (w&7), n half (w>>3) -> acc2[4][4]
    // g1: warps 0-11, m-frag (w%3), n 16-slice (w/3)      -> accX[2][4]
    // g0: warps 12-15, m-frag 0,  n 16-slice (w-12)       -> accX[2][4]
    float acc2[4][4], accX[2][4];
#pragma unroll
    for (int ni = 0; ni < 4; ni++)
#pragma unroll
        for (int di = 0; di < 4; di++) {
            acc2[ni][di] = 0.f;
            if (ni < 2) accX[ni][di] = 0.f;
        }

    // prologue: W0, W1 in flight; gen chunk0; wait W0; publish
    prefetch_w(0, 0, 0, sb, tid);
    asm volatile("cp.async.commit_group;" ::: "memory");
    prefetch_w(0, 1, 1, sb, tid);
    asm volatile("cp.async.commit_group;" ::: "memory");
    __syncthreads();                        // staging visible for gen
    gen_chunk(0, c_grp[0], 0, nzv, smemf, smem, P_OFF, tid);
    asm volatile("cp.async.wait_group 1;" ::: "memory");   // W0 done
    __syncthreads();                        // publish P0 + W0

    // invariant at top of iter c: P[c&1] + W[c] visible to all; W[c+1] in flight
    for (int c = 0; c < 960; c++) {
        const int cn = c + 2;
        if (cn < 960) prefetch_w(cn >> 6, cn & 63, cn % 3, sb, tid);
        asm volatile("cp.async.commit_group;" ::: "memory");
        const int cg = c + 1;
        if (cg < 960)
            gen_chunk(cg >> 6, c_grp[cg >> 6], cg & 63, nzv, smemf, smem,
                      P_OFF + (cg & 1) * P_STRIDE, tid);
        asm volatile("cp.async.wait_group 1;" ::: "memory");   // W[c+1] landed
        const int g = c_grp[c >> 6];
        const uint32_t pP = sb + P_OFF + (c & 1) * P_STRIDE;
        const uint32_t pW = sb + W_OFF + (c % 3) * W_STRIDE;
        if (g == 2) {
            warp_mma<2>(acc2, (w & 7) * 16, (w >> 3) * 32, pP, pW, lane);
        } else if (g == 1) {
            if (w < 12) warp_mma<1>(accX, (w % 3) * 16, (w / 3) * 16, pP, pW, lane);
        } else {
            if (w >= 12) warp_mma<1>(accX, 0, (w - 12) * 16, pP, pW, lane);
        }
        __syncthreads();   // publish P[(c+1)&1] and W[c+1]
    }

    // ---- epilogue (D frag: row=(l>>2)+8*(di>>1), col=2*(l&3)+(di&1)); scale by 2^-10 ----
    {
        const int m0 = (w & 7) * 16, n0 = (w >> 3) * 32;
#pragma unroll
        for (int ni = 0; ni < 4; ni++)
#pragma unroll
            for (int di = 0; di < 4; di++) {
                int row = m0 + (lane >> 2) + (di >> 1) * 8;
                int col = n0 + ni * 8 + (lane & 3) * 2 + (di & 1);
                if (row < 126) {
                    int z = row / 9, u = row - z * 9;
                    if (z < nzv)
                        out[(size_t)(z0 + z) * 832 + 256 + col * 9 + u] = acc2[ni][di] * SCL;
                }
            }
    }
    if (w < 12) {
        const int m0 = (w % 3) * 16, n0 = (w / 3) * 16;
#pragma unroll
        for (int ni = 0; ni < 2; ni++)
#pragma unroll
            for (int di = 0; di < 4; di++) {
                int row = m0 + (lane >> 2) + (di >> 1) * 8;
                int col = n0 + ni * 8 + (lane & 3) * 2 + (di & 1);
                if (row < 42) {
                    int z = row / 3, u = row - z * 3;
                    if (z < nzv)
                        out[(size_t)(z0 + z) * 832 + 64 + col * 3 + u] = accX[ni][di] * SCL;
                }
            }
    } else {
        const int n0 = (w - 12) * 16;
#pragma unroll
        for (int ni = 0; ni < 2; ni++)
#pragma unroll
            for (int di = 0; di < 4; di++) {
                int row = (lane >> 2) + (di >> 1) * 8;
                int col = n0 + ni * 8 + (lane & 3) * 2 + (di & 1);
                if (row < nzv)
                    out[(size_t)(z0 + row) * 832 + col] = accX[ni][di] * SCL;
            }
    }
}

extern "C" void kernel_launch(void* const* d_in, const int* in_sizes, int n_in,
                              void* d_out, int out_size) {
    const float* x1 = (const float*)d_in[0];
    const float* x2 = (const float*)d_in[1];
    const float* w  = (const float*)d_in[2];
    float* out = (float*)d_out;

    prep_w<<<(WTE + 255) / 256, 256>>>(w);

    static int attr_set = 0;
    if (!attr_set) {
        cudaFuncSetAttribute(tp_hmma_kernel, cudaFuncAttributeMaxDynamicSharedMemorySize, SMEM_TOT);
        attr_set = 1;
    }
    tp_hmma_kernel<<<293, NTHR, SMEM_TOT>>>(x1, x2, out);
}

// round 15
// speedup vs baseline: 1.8868x; 1.2589x over previous
#include <cuda_runtime.h>
#include <cuda_fp16.h>
#include <cstdint>

#define WTE (15 * 64 * 4096)

// fp16 W tiles [p][a][c][b], pre-scaled by 1024 (epilogue multiplies by 2^-10)
__device__ __align__(16) __half g_Wf[WTE];

// group of each path: 0 -> Lout0, 1 -> Lout1, 2 -> Lout2
__constant__ int c_grp[15] = {0,1,2,1,2,0,1,1,2,2,1,2,2,0,1};

__global__ void prep_w(const float* __restrict__ w) {
    int d = blockIdx.x * 256 + threadIdx.x;
    if (d >= WTE) return;
    int p = d >> 18, a = (d >> 12) & 63, c = (d >> 6) & 63, b = d & 63;
    float f = w[(p << 18) | (c << 12) | (a << 6) | b];
    g_Wf[d] = __float2half(f * 1024.0f);
}

// ---------- smem byte layout (1 CTA, 512 threads) ----------
// x1: [0, 46656)   (14*833*4)
// x2T: [46656, 93696)  (14*840*4)
// P: 2 stages * 128 rows * 304B = 2*38912 -> [93696, 171520)
// W: 2 slots * 64 rows * 304B = 2*19456  -> [171520, 210432)
#define ROWB     304
#define P_OFF    93696
#define P_STRIDE 38912
#define W_OFF    171520
#define W_STRIDE 19456
#define SMEM_TOT 210432
#define NTHR     512
#define NCHUNK   480

__device__ __forceinline__ uint32_t smem_u32(const void* p) {
    uint32_t a;
    asm("{ .reg .u64 t; cvta.to.shared.u64 t, %1; cvt.u32.u64 %0, t; }" : "=r"(a) : "l"(p));
    return a;
}

#define LDSM4(r, addr) asm volatile( \
    "ldmatrix.sync.aligned.m8n8.x4.shared.b16 {%0,%1,%2,%3}, [%4];" \
    : "=r"((r)[0]), "=r"((r)[1]), "=r"((r)[2]), "=r"((r)[3]) : "r"(addr))

#define MMAF(d, a, bb0, bb1) asm volatile( \
    "mma.sync.aligned.m16n8k16.row.col.f32.f16.f16.f32 " \
    "{%0,%1,%2,%3}, {%4,%5,%6,%7}, {%8,%9}, {%0,%1,%2,%3};" \
    : "+f"((d)[0]), "+f"((d)[1]), "+f"((d)[2]), "+f"((d)[3]) \
    : "r"((a)[0]), "r"((a)[1]), "r"((a)[2]), "r"((a)[3]), "r"(bb0), "r"(bb1))

// one m-frag (16 rows) x NF n16-frags, single fp16 pass, K=128 (8 k-steps)
template<int NF>
__device__ __forceinline__ void warp_mma(float (*acc)[4], int m0, int n0,
                                         uint32_t pP, uint32_t pW, int lane) {
    const uint32_t aoff = (uint32_t)((lane & 15) * ROWB + ((lane >> 4) << 4));
    const uint32_t boff = (uint32_t)(((lane & 7) + ((lane >> 4) & 1) * 8) * ROWB + (lane & 8) * 2);
#pragma unroll
    for (int ks = 0; ks < 8; ks++) {
        const uint32_t kb = ks * 32;
        uint32_t ah[4];
        LDSM4(ah, pP + (uint32_t)(m0 * ROWB) + kb + aoff);
        uint32_t bh[NF][4];
#pragma unroll
        for (int nj = 0; nj < NF; nj++)
            LDSM4(bh[nj], pW + (uint32_t)((n0 + nj * 16) * ROWB) + kb + boff);
#pragma unroll
        for (int nj = 0; nj < NF; nj++)
#pragma unroll
            for (int s = 0; s < 2; s++)
                MMAF(acc[nj * 2 + s], ah, bh[nj][s * 2], bh[nj][s * 2 + 1]);
    }
}

// 512 threads issue the 16KB W double-tile (p, a0) + (p, a0+1) via cp.async
__device__ __forceinline__ void prefetch_w(int p, int a0, int slot, uint32_t sb, int tid) {
    const int cR = tid >> 3, seg = tid & 7;
#pragma unroll
    for (int as_ = 0; as_ < 2; as_++) {
        const size_t tile = ((size_t)(p * 64 + a0 + as_)) << 12;
        const __half* src = g_Wf + tile + cR * 64 + seg * 8;
        uint32_t dst = sb + W_OFF + slot * W_STRIDE + cR * ROWB + as_ * 128 + seg * 16;
        asm volatile("cp.async.cg.shared.global [%0], [%1], 16;" :: "r"(dst), "l"(src));
    }
}

__device__ __forceinline__ float4 f4mul(float s, float4 v) {
    return make_float4(s * v.x, s * v.y, s * v.z, s * v.w);
}
__device__ __forceinline__ float4 f4fma(float s, float4 v, float4 c) {
    return make_float4(fmaf(s, v.x, c.x), fmaf(s, v.y, c.y), fmaf(s, v.z, c.z), fmaf(s, v.w, c.w));
}
__device__ __forceinline__ float4 f4sub2(float s1, float4 a, float s2, float4 b) {
    return make_float4(s1 * a.x - s2 * b.x, s1 * a.y - s2 * b.y,
                       s1 * a.z - s2 * b.z, s1 * a.w - s2 * b.w);
}
__device__ __forceinline__ float4 ld4(const float* p) { return *(const float4*)p; }
__device__ __forceinline__ void st4(char* smemc, uint32_t off, float4 v) {
    __half2 h0 = __floats2half2_rn(v.x, v.y);
    __half2 h1 = __floats2half2_rn(v.z, v.w);
    uint2 u;
    u.x = *(uint32_t*)&h0;
    u.y = *(uint32_t*)&h1;
    *(uint2*)(smemc + off) = u;
}
#define DOT3(r0, r1, r2, m0, m1, m2) f4fma(m2, r2, f4fma(m1, r1, f4mul(m0, r0)))

// u-triple fused P generation for a DOUBLE chunk (a0, a0+1).
// Task = (vrow, a_sel, b-quad). k-col = a_sel*64 + b.
__device__ __forceinline__ void gen_chunk(int p, int g, int a0, int nzv,
                                          const float* smemf, char* smemc,
                                          uint32_t pdst, int tid) {
    if (g == 2) {
        for (int t = tid; t < 1344; t += NTHR) {
            const int vr = t >> 5, r = t & 31;
            const int as_ = r >> 4, b0 = (r & 15) << 2;
            const int a = a0 + as_;
            const int zr = vr / 3, j = vr - zr * 3;
            const int z = (zr > nzv - 1) ? nzv - 1 : zr;
            const float* ax = smemf + z * 833;
            const float* bz = smemf + 11664 + z * 840;
            const float* av = ax + 64 + 3 * a;
            const float* am = ax + 256 + 9 * a;
            float4 v0, v1, v2;
            switch (p) {
            case 2: { float A = ax[a];
                v0 = f4mul(A, ld4(bz + 256 + j * 64 + b0));
                v1 = f4mul(A, ld4(bz + 256 + (j + 3) * 64 + b0));
                v2 = f4mul(A, ld4(bz + 256 + (j + 6) * 64 + b0)); } break;
            case 4: { float4 s = ld4(bz + 64 + j * 64 + b0);
                v0 = f4mul(av[0], s); v1 = f4mul(av[1], s); v2 = f4mul(av[2], s); } break;
            case 8: { int g1 = (j + 1) % 3, g2 = (j + 2) % 3;
                float A1 = av[g1], A2 = av[g2];
                v0 = f4sub2(A1, ld4(bz + 256 + g2 * 64 + b0), A2, ld4(bz + 256 + g1 * 64 + b0));
                v1 = f4sub2(A1, ld4(bz + 256 + (3 + g2) * 64 + b0), A2, ld4(bz + 256 + (3 + g1) * 64 + b0));
                v2 = f4sub2(A1, ld4(bz + 256 + (6 + g2) * 64 + b0), A2, ld4(bz + 256 + (6 + g1) * 64 + b0)); } break;
            case 9: { float4 s = ld4(bz + b0);
                v0 = f4mul(am[j], s); v1 = f4mul(am[j + 3], s); v2 = f4mul(am[j + 6], s); } break;
            case 11: { int g1 = (j + 1) % 3, g2 = (j + 2) % 3;
                float4 qa = ld4(bz + 64 + g2 * 64 + b0), qb = ld4(bz + 64 + g1 * 64 + b0);
                v0 = f4sub2(am[g1], qa, am[g2], qb);
                v1 = f4sub2(am[3 + g1], qa, am[3 + g2], qb);
                v2 = f4sub2(am[6 + g1], qa, am[6 + g2], qb); } break;
            default: { // p12, f=j
                float4 q0 = ld4(bz + 256 + (3 * j) * 64 + b0);
                float4 q1 = ld4(bz + 256 + (3 * j + 1) * 64 + b0);
                float4 q2 = ld4(bz + 256 + (3 * j + 2) * 64 + b0);
                v0 = DOT3(q0, q1, q2, am[0], am[1], am[2]);
                v1 = DOT3(q0, q1, q2, am[3], am[4], am[5]);
                v2 = DOT3(q0, q1, q2, am[6], am[7], am[8]); } break;
            }
            const uint32_t base = pdst + (uint32_t)((zr * 9 + j) * ROWB) + as_ * 128 + b0 * 2;
            st4(smemc, base, v0);
            st4(smemc, base + 3 * ROWB, v1);
            st4(smemc, base + 6 * ROWB, v2);
        }
    } else if (g == 1) {
        for (int t = tid; t < 448; t += NTHR) {
            const int zr = t >> 5, r = t & 31;
            const int as_ = r >> 4, b0 = (r & 15) << 2;
            const int a = a0 + as_;
            const int z = (zr > nzv - 1) ? nzv - 1 : zr;
            const float* ax = smemf + z * 833;
            const float* bz = smemf + 11664 + z * 840;
            const float* av = ax + 64 + 3 * a;
            const float* am = ax + 256 + 9 * a;
            float4 v0, v1, v2;
            switch (p) {
            case 1: { float A = ax[a];
                v0 = f4mul(A, ld4(bz + 64 + b0));
                v1 = f4mul(A, ld4(bz + 128 + b0));
                v2 = f4mul(A, ld4(bz + 192 + b0)); } break;
            case 3: { float4 s = ld4(bz + b0);
                v0 = f4mul(av[0], s); v1 = f4mul(av[1], s); v2 = f4mul(av[2], s); } break;
            case 6: { float4 c0 = ld4(bz + 64 + b0), c1 = ld4(bz + 128 + b0), c2 = ld4(bz + 192 + b0);
                v0 = f4sub2(av[1], c2, av[2], c1);
                v1 = f4sub2(av[2], c0, av[0], c2);
                v2 = f4sub2(av[0], c1, av[1], c0); } break;
            case 7: {
                v0 = DOT3(ld4(bz + 256 + b0), ld4(bz + 256 + 64 + b0), ld4(bz + 256 + 128 + b0),
                          av[0], av[1], av[2]);
                v1 = DOT3(ld4(bz + 256 + 192 + b0), ld4(bz + 256 + 256 + b0), ld4(bz + 256 + 320 + b0),
                          av[0], av[1], av[2]);
                v2 = DOT3(ld4(bz + 256 + 384 + b0), ld4(bz + 256 + 448 + b0), ld4(bz + 256 + 512 + b0),
                          av[0], av[1], av[2]); } break;
            case 10: { float4 c0 = ld4(bz + 64 + b0), c1 = ld4(bz + 128 + b0), c2 = ld4(bz + 192 + b0);
                v0 = DOT3(c0, c1, c2, am[0], am[1], am[2]);
                v1 = DOT3(c0, c1, c2, am[3], am[4], am[5]);
                v2 = DOT3(c0, c1, c2, am[6], am[7], am[8]); } break;
            default: { // p14
                v0 = make_float4(0.f, 0.f, 0.f, 0.f); v1 = v0; v2 = v0;
#pragma unroll
                for (int i = 0; i < 3; i++) {
                    float4 r0 = ld4(bz + 256 + i * 64 + b0);
                    float4 r3 = ld4(bz + 256 + (3 + i) * 64 + b0);
                    float4 r6 = ld4(bz + 256 + (6 + i) * 64 + b0);
                    v0.x += am[3+i]*r6.x - am[6+i]*r3.x; v0.y += am[3+i]*r6.y - am[6+i]*r3.y;
                    v0.z += am[3+i]*r6.z - am[6+i]*r3.z; v0.w += am[3+i]*r6.w - am[6+i]*r3.w;
                    v1.x += am[6+i]*r0.x - am[i]*r6.x;   v1.y += am[6+i]*r0.y - am[i]*r6.y;
                    v1.z += am[6+i]*r0.z - am[i]*r6.z;   v1.w += am[6+i]*r0.w - am[i]*r6.w;
                    v2.x += am[i]*r3.x - am[3+i]*r0.x;   v2.y += am[i]*r3.y - am[3+i]*r0.y;
                    v2.z += am[i]*r3.z - am[3+i]*r0.z;   v2.w += am[i]*r3.w - am[3+i]*r0.w;
                } } break;
            }
            const uint32_t base = pdst + (uint32_t)((zr * 3) * ROWB) + as_ * 128 + b0 * 2;
            st4(smemc, base, v0);
            st4(smemc, base + ROWB, v1);
            st4(smemc, base + 2 * ROWB, v2);
        }
    } else {
        for (int t = tid; t < 448; t += NTHR) {
            const int zr = t >> 5, r = t & 31;
            const int as_ = r >> 4, b0 = (r & 15) << 2;
            const int a = a0 + as_;
            const int z = (zr > nzv - 1) ? nzv - 1 : zr;
            const float* ax = smemf + z * 833;
            const float* bz = smemf + 11664 + z * 840;
            const float* av = ax + 64 + 3 * a;
            const float* am = ax + 256 + 9 * a;
            float4 v0;
            switch (p) {
            case 0: v0 = f4mul(ax[a], ld4(bz + b0)); break;
            case 5: v0 = DOT3(ld4(bz + 64 + b0), ld4(bz + 128 + b0), ld4(bz + 192 + b0),
                              av[0], av[1], av[2]); break;
            default: { // p13
                v0 = make_float4(0.f, 0.f, 0.f, 0.f);
#pragma unroll
                for (int t2 = 0; t2 < 9; t2++)
                    v0 = f4fma(am[t2], ld4(bz + 256 + t2 * 64 + b0), v0);
            } break;
            }
            st4(smemc, pdst + (uint32_t)(zr * ROWB) + as_ * 128 + b0 * 2, v0);
        }
    }
}

__global__ void __launch_bounds__(NTHR, 1)
tp_hmma_kernel(const float* __restrict__ x1, const float* __restrict__ x2,
               float* __restrict__ out) {
    extern __shared__ char smem[];
    float* smemf = (float*)smem;
    const int tid = threadIdx.x, w = tid >> 5, lane = tid & 31;
    const int z0 = blockIdx.x * 14;
    const int nzv = min(14, 4096 - z0);
    const uint32_t sb = smem_u32(smem);
    const float SCL = 1.0f / 1024.0f;   // undo the W*1024 prescale

    // stage x1 (natural, stride 833) and x2 (component-major, stride 840)
    for (int i = tid; i < 14 * 832; i += NTHR) {
        int z = i / 832, f = i - z * 832;
        int zg = z0 + z; if (zg > 4095) zg = 4095;
        smemf[z * 833 + f] = x1[(size_t)zg * 832 + f];
        float v2 = x2[(size_t)zg * 832 + f];
        int d;
        if (f < 64) d = f;
        else if (f < 256) { int g = f - 64; d = 64 + (g % 3) * 64 + g / 3; }
        else { int g = f - 256; d = 256 + (g % 9) * 64 + g / 9; }
        smemf[11664 + z * 840 + d] = v2;
    }

    // 16 warps. g2: all warps, m-frag (w&7), n half (w>>3) -> acc2[4][4]
    // g1: warps 0-11, m-frag (w%3), n 16-slice (w/3)      -> accX[2][4]
    // g0: warps 12-15, m-frag 0,  n 16-slice (w-12)       -> accX[2][4]
    float acc2[4][4], accX[2][4];
#pragma unroll
    for (int ni = 0; ni < 4; ni++)
#pragma unroll
        for (int di = 0; di < 4; di++) {
            acc2[ni][di] = 0.f;
            if (ni < 2) accX[ni][di] = 0.f;
        }

    // prologue: W0 in flight; stage visible; gen P0; wait; publish
    prefetch_w(0, 0, 0, sb, tid);
    asm volatile("cp.async.commit_group;" ::: "memory");
    __syncthreads();                        // staging visible for gen
    gen_chunk(0, c_grp[0], 0, nzv, smemf, smem, P_OFF, tid);
    asm volatile("cp.async.wait_group 0;" ::: "memory");   // W0 landed
    __syncthreads();                        // publish P0 + W0

    // invariant at top of iter c: P[c&1] + W[c&1] visible to all
    for (int c = 0; c < NCHUNK; c++) {
        const int cg = c + 1;
        if (cg < NCHUNK) {
            prefetch_w(cg >> 5, (cg & 31) * 2, cg & 1, sb, tid);
            asm volatile("cp.async.commit_group;" ::: "memory");
            gen_chunk(cg >> 5, c_grp[cg >> 5], (cg & 31) * 2, nzv, smemf, smem,
                      P_OFF + (cg & 1) * P_STRIDE, tid);
        }
        asm volatile("cp.async.wait_group 0;" ::: "memory");   // W[c+1] landed
        const int g = c_grp[c >> 5];
        const uint32_t pP = sb + P_OFF + (c & 1) * P_STRIDE;
        const uint32_t pW = sb + W_OFF + (c & 1) * W_STRIDE;
        if (g == 2) {
            warp_mma<2>(acc2, (w & 7) * 16, (w >> 3) * 32, pP, pW, lane);
        } else if (g == 1) {
            if (w < 12) warp_mma<1>(accX, (w % 3) * 16, (w / 3) * 16, pP, pW, lane);
        } else {
            if (w >= 12) warp_mma<1>(accX, 0, (w - 12) * 16, pP, pW, lane);
        }
        __syncthreads();   // publish P[(c+1)&1] and W[(c+1)&1]
    }

    // ---- epilogue (D frag: row=(l>>2)+8*(di>>1), col=2*(l&3)+(di&1)); scale by 2^-10 ----
    {
        const int m0 = (w & 7) * 16, n0 = (w >> 3) * 32;
#pragma unroll
        for (int ni = 0; ni < 4; ni++)
#pragma unroll
            for (int di = 0; di < 4; di++) {
                int row = m0 + (lane >> 2) + (di >> 1) * 8;
                int col = n0 + ni * 8 + (lane & 3) * 2 + (di & 1);
                if (row < 126) {
                    int z = row / 9, u = row - z * 9;
                    if (z < nzv)
                        out[(size_t)(z0 + z) * 832 + 256 + col * 9 + u] = acc2[ni][di] * SCL;
                }
            }
    }
    if (w < 12) {
        const int m0 = (w % 3) * 16, n0 = (w / 3) * 16;
#pragma unroll
        for (int ni = 0; ni < 2; ni++)
#pragma unroll
            for (int di = 0; di < 4; di++) {
                int row = m0 + (lane >> 2) + (di >> 1) * 8;
                int col = n0 + ni * 8 + (lane & 3) * 2 + (di & 1);
                if (row < 42) {
                    int z = row / 3, u = row - z * 3;
                    if (z < nzv)
                        out[(size_t)(z0 + z) * 832 + 64 + col * 3 + u] = accX[ni][di] * SCL;
                }
            }
    } else {
        const int n0 = (w - 12) * 16;
#pragma unroll
        for (int ni = 0; ni < 2; ni++)
#pragma unroll
            for (int di = 0; di < 4; di++) {
                int row = (lane >> 2) + (di >> 1) * 8;
                int col = n0 + ni * 8 + (lane & 3) * 2 + (di & 1);
                if (row < nzv)
                    out[(size_t)(z0 + row) * 832 + col] = accX[ni][di] * SCL;
            }
    }
}

extern "C" void kernel_launch(void* const* d_in, const int* in_sizes, int n_in,
                              void* d_out, int out_size) {
    const float* x1 = (const float*)d_in[0];
    const float* x2 = (const float*)d_in[1];
    const float* w  = (const float*)d_in[2];
    float* out = (float*)d_out;

    prep_w<<<(WTE + 255) / 256, 256>>>(w);

    static int attr_set = 0;
    if (!attr_set) {
        cudaFuncSetAttribute(tp_hmma_kernel, cudaFuncAttributeMaxDynamicSharedMemorySize, SMEM_TOT);
        attr_set = 1;
    }
    tp_hmma_kernel<<<293, NTHR, SMEM_TOT>>>(x1, x2, out);
}

// round 16
// speedup vs baseline: 1.9402x; 1.0283x over previous
#include <cuda_runtime.h>
#include <cuda_fp16.h>
#include <cstdint>

#define WTE (15 * 64 * 4096)

// fp16 W tiles [p][a][c][b], pre-scaled by 1024 (epilogue multiplies by 2^-10)
__device__ __align__(16) __half g_Wf[WTE];

// group of each path: 0 -> Lout0, 1 -> Lout1, 2 -> Lout2
__constant__ int c_grp[15] = {0,1,2,1,2,0,1,1,2,2,1,2,2,0,1};

__global__ void prep_w(const float* __restrict__ w) {
    int d = blockIdx.x * 256 + threadIdx.x;
    if (d >= WTE) return;
    int p = d >> 18, a = (d >> 12) & 63, c = (d >> 6) & 63, b = d & 63;
    float f = w[(p << 18) | (c << 12) | (a << 6) | b];
    g_Wf[d] = __float2half(f * 1024.0f);
}

// ---------- smem byte layout (1 CTA, 512 threads) ----------
// x1 fp32: [0, 46656)            (14*833*4)
// x2T fp16: [46656, 70400)       (14*848*2 = 23744)
// P: 2 stages * 128 rows * 304B -> [70400, 148224)
// W: 2 slots * 64 rows * 304B   -> [148224, 187136)
#define ROWB     304
#define X2H_OFF  46656
#define X2H_STR  848
#define P_OFF    70400
#define P_STRIDE 38912
#define W_OFF    148224
#define W_STRIDE 19456
#define SMEM_TOT 187136
#define NTHR     512
#define NCHUNK   480

__device__ __forceinline__ uint32_t smem_u32(const void* p) {
    uint32_t a;
    asm("{ .reg .u64 t; cvta.to.shared.u64 t, %1; cvt.u32.u64 %0, t; }" : "=r"(a) : "l"(p));
    return a;
}

#define LDSM4(r, addr) asm volatile( \
    "ldmatrix.sync.aligned.m8n8.x4.shared.b16 {%0,%1,%2,%3}, [%4];" \
    : "=r"((r)[0]), "=r"((r)[1]), "=r"((r)[2]), "=r"((r)[3]) : "r"(addr))

#define MMAF(d, a, bb0, bb1) asm volatile( \
    "mma.sync.aligned.m16n8k16.row.col.f32.f16.f16.f32 " \
    "{%0,%1,%2,%3}, {%4,%5,%6,%7}, {%8,%9}, {%0,%1,%2,%3};" \
    : "+f"((d)[0]), "+f"((d)[1]), "+f"((d)[2]), "+f"((d)[3]) \
    : "r"((a)[0]), "r"((a)[1]), "r"((a)[2]), "r"((a)[3]), "r"(bb0), "r"(bb1))

// g2 k-split: one m-frag x full n=64 (4 n16), 4 k-steps starting at ks0
__device__ __forceinline__ void warp_mma_g2(float (*acc)[4], int m0, int ks0,
                                            uint32_t pP, uint32_t pW, int lane) {
    const uint32_t aoff = (uint32_t)((lane & 15) * ROWB + ((lane >> 4) << 4));
    const uint32_t boff = (uint32_t)(((lane & 7) + ((lane >> 4) & 1) * 8) * ROWB + (lane & 8) * 2);
#pragma unroll
    for (int k = 0; k < 4; k++) {
        const uint32_t kb = (uint32_t)(ks0 + k) * 32;
        uint32_t ah[4];
        LDSM4(ah, pP + (uint32_t)(m0 * ROWB) + kb + aoff);
        uint32_t bh[4][4];
#pragma unroll
        for (int nj = 0; nj < 4; nj++)
            LDSM4(bh[nj], pW + (uint32_t)((nj * 16) * ROWB) + kb + boff);
#pragma unroll
        for (int nj = 0; nj < 4; nj++)
#pragma unroll
            for (int s = 0; s < 2; s++)
                MMAF(acc[nj * 2 + s], ah, bh[nj][s * 2], bh[nj][s * 2 + 1]);
    }
}

// g1/g0: one m-frag x 1 n16, all 8 k-steps
__device__ __forceinline__ void warp_mma_x(float (*acc)[4], int m0, int n0,
                                           uint32_t pP, uint32_t pW, int lane) {
    const uint32_t aoff = (uint32_t)((lane & 15) * ROWB + ((lane >> 4) << 4));
    const uint32_t boff = (uint32_t)(((lane & 7) + ((lane >> 4) & 1) * 8) * ROWB + (lane & 8) * 2);
#pragma unroll
    for (int ks = 0; ks < 8; ks++) {
        const uint32_t kb = ks * 32;
        uint32_t ah[4];
        LDSM4(ah, pP + (uint32_t)(m0 * ROWB) + kb + aoff);
        uint32_t bh[4];
        LDSM4(bh, pW + (uint32_t)(n0 * ROWB) + kb + boff);
#pragma unroll
        for (int s = 0; s < 2; s++)
            MMAF(acc[s], ah, bh[s * 2], bh[s * 2 + 1]);
    }
}

// 512 threads issue the 16KB W double-tile (p, a0) + (p, a0+1) via cp.async
__device__ __forceinline__ void prefetch_w(int p, int a0, int slot, uint32_t sb, int tid) {
    const int cR = tid >> 3, seg = tid & 7;
#pragma unroll
    for (int as_ = 0; as_ < 2; as_++) {
        const size_t tile = ((size_t)(p * 64 + a0 + as_)) << 12;
        const __half* src = g_Wf + tile + cR * 64 + seg * 8;
        uint32_t dst = sb + W_OFF + slot * W_STRIDE + cR * ROWB + as_ * 128 + seg * 16;
        asm volatile("cp.async.cg.shared.global [%0], [%1], 16;" :: "r"(dst), "l"(src));
    }
}

__device__ __forceinline__ float4 f4mul(float s, float4 v) {
    return make_float4(s * v.x, s * v.y, s * v.z, s * v.w);
}
__device__ __forceinline__ float4 f4fma(float s, float4 v, float4 c) {
    return make_float4(fmaf(s, v.x, c.x), fmaf(s, v.y, c.y), fmaf(s, v.z, c.z), fmaf(s, v.w, c.w));
}
__device__ __forceinline__ float4 f4sub2(float s1, float4 a, float s2, float4 b) {
    return make_float4(s1 * a.x - s2 * b.x, s1 * a.y - s2 * b.y,
                       s1 * a.z - s2 * b.z, s1 * a.w - s2 * b.w);
}
// load 4 fp16 (8B) from smem, convert to float4
__device__ __forceinline__ float4 ld4h(const __half* p) {
    uint2 u = *(const uint2*)p;
    __half2 h0 = *(__half2*)&u.x;
    __half2 h1 = *(__half2*)&u.y;
    float2 f0 = __half22float2(h0);
    float2 f1 = __half22float2(h1);
    return make_float4(f0.x, f0.y, f1.x, f1.y);
}
__device__ __forceinline__ void st4(char* smemc, uint32_t off, float4 v) {
    __half2 h0 = __floats2half2_rn(v.x, v.y);
    __half2 h1 = __floats2half2_rn(v.z, v.w);
    uint2 u;
    u.x = *(uint32_t*)&h0;
    u.y = *(uint32_t*)&h1;
    *(uint2*)(smemc + off) = u;
}
#define DOT3(r0, r1, r2, m0, m1, m2) f4fma(m2, r2, f4fma(m1, r1, f4mul(m0, r0)))

// u-triple fused P generation for a DOUBLE chunk (a0, a0+1). x2 in fp16.
__device__ __forceinline__ void gen_chunk(int p, int g, int a0, int nzv,
                                          const float* smemf, const __half* smemh,
                                          char* smemc, uint32_t pdst, int tid) {
    if (g == 2) {
        for (int t = tid; t < 1344; t += NTHR) {
            const int vr = t >> 5, r = t & 31;
            const int as_ = r >> 4, b0 = (r & 15) << 2;
            const int a = a0 + as_;
            const int zr = vr / 3, j = vr - zr * 3;
            const int z = (zr > nzv - 1) ? nzv - 1 : zr;
            const float* ax = smemf + z * 833;
            const __half* bz = smemh + z * X2H_STR;
            const float* av = ax + 64 + 3 * a;
            const float* am = ax + 256 + 9 * a;
            float4 v0, v1, v2;
            switch (p) {
            case 2: { float A = ax[a];
                v0 = f4mul(A, ld4h(bz + 256 + j * 64 + b0));
                v1 = f4mul(A, ld4h(bz + 256 + (j + 3) * 64 + b0));
                v2 = f4mul(A, ld4h(bz + 256 + (j + 6) * 64 + b0)); } break;
            case 4: { float4 s = ld4h(bz + 64 + j * 64 + b0);
                v0 = f4mul(av[0], s); v1 = f4mul(av[1], s); v2 = f4mul(av[2], s); } break;
            case 8: { int g1 = (j + 1) % 3, g2 = (j + 2) % 3;
                float A1 = av[g1], A2 = av[g2];
                v0 = f4sub2(A1, ld4h(bz + 256 + g2 * 64 + b0), A2, ld4h(bz + 256 + g1 * 64 + b0));
                v1 = f4sub2(A1, ld4h(bz + 256 + (3 + g2) * 64 + b0), A2, ld4h(bz + 256 + (3 + g1) * 64 + b0));
                v2 = f4sub2(A1, ld4h(bz + 256 + (6 + g2) * 64 + b0), A2, ld4h(bz + 256 + (6 + g1) * 64 + b0)); } break;
            case 9: { float4 s = ld4h(bz + b0);
                v0 = f4mul(am[j], s); v1 = f4mul(am[j + 3], s); v2 = f4mul(am[j + 6], s); } break;
            case 11: { int g1 = (j + 1) % 3, g2 = (j + 2) % 3;
                float4 qa = ld4h(bz + 64 + g2 * 64 + b0), qb = ld4h(bz + 64 + g1 * 64 + b0);
                v0 = f4sub2(am[g1], qa, am[g2], qb);
                v1 = f4sub2(am[3 + g1], qa, am[3 + g2], qb);
                v2 = f4sub2(am[6 + g1], qa, am[6 + g2], qb); } break;
            default: { // p12, f=j
                float4 q0 = ld4h(bz + 256 + (3 * j) * 64 + b0);
                float4 q1 = ld4h(bz + 256 + (3 * j + 1) * 64 + b0);
                float4 q2 = ld4h(bz + 256 + (3 * j + 2) * 64 + b0);
                v0 = DOT3(q0, q1, q2, am[0], am[1], am[2]);
                v1 = DOT3(q0, q1, q2, am[3], am[4], am[5]);
                v2 = DOT3(q0, q1, q2, am[6], am[7], am[8]); } break;
            }
            const uint32_t base = pdst + (uint32_t)((zr * 9 + j) * ROWB) + as_ * 128 + b0 * 2;
            st4(smemc, base, v0);
            st4(smemc, base + 3 * ROWB, v1);
            st4(smemc, base + 6 * ROWB, v2);
        }
    } else if (g == 1) {
        for (int t = tid; t < 448; t += NTHR) {
            const int zr = t >> 5, r = t & 31;
            const int as_ = r >> 4, b0 = (r & 15) << 2;
            const int a = a0 + as_;
            const int z = (zr > nzv - 1) ? nzv - 1 : zr;
            const float* ax = smemf + z * 833;
            const __half* bz = smemh + z * X2H_STR;
            const float* av = ax + 64 + 3 * a;
            const float* am = ax + 256 + 9 * a;
            float4 v0, v1, v2;
            switch (p) {
            case 1: { float A = ax[a];
                v0 = f4mul(A, ld4h(bz + 64 + b0));
                v1 = f4mul(A, ld4h(bz + 128 + b0));
                v2 = f4mul(A, ld4h(bz + 192 + b0)); } break;
            case 3: { float4 s = ld4h(bz + b0);
                v0 = f4mul(av[0], s); v1 = f4mul(av[1], s); v2 = f4mul(av[2], s); } break;
            case 6: { float4 c0 = ld4h(bz + 64 + b0), c1 = ld4h(bz + 128 + b0), c2 = ld4h(bz + 192 + b0);
                v0 = f4sub2(av[1], c2, av[2], c1);
                v1 = f4sub2(av[2], c0, av[0], c2);
                v2 = f4sub2(av[0], c1, av[1], c0); } break;
            case 7: {
                v0 = DOT3(ld4h(bz + 256 + b0), ld4h(bz + 256 + 64 + b0), ld4h(bz + 256 + 128 + b0),
                          av[0], av[1], av[2]);
                v1 = DOT3(ld4h(bz + 256 + 192 + b0), ld4h(bz + 256 + 256 + b0), ld4h(bz + 256 + 320 + b0),
                          av[0], av[1], av[2]);
                v2 = DOT3(ld4h(bz + 256 + 384 + b0), ld4h(bz + 256 + 448 + b0), ld4h(bz + 256 + 512 + b0),
                          av[0], av[1], av[2]); } break;
            case 10: { float4 c0 = ld4h(bz + 64 + b0), c1 = ld4h(bz + 128 + b0), c2 = ld4h(bz + 192 + b0);
                v0 = DOT3(c0, c1, c2, am[0], am[1], am[2]);
                v1 = DOT3(c0, c1, c2, am[3], am[4], am[5]);
                v2 = DOT3(c0, c1, c2, am[6], am[7], am[8]); } break;
            default: { // p14
                v0 = make_float4(0.f, 0.f, 0.f, 0.f); v1 = v0; v2 = v0;
#pragma unroll
                for (int i = 0; i < 3; i++) {
                    float4 r0 = ld4h(bz + 256 + i * 64 + b0);
                    float4 r3 = ld4h(bz + 256 + (3 + i) * 64 + b0);
                    float4 r6 = ld4h(bz + 256 + (6 + i) * 64 + b0);
                    v0.x += am[3+i]*r6.x - am[6+i]*r3.x; v0.y += am[3+i]*r6.y - am[6+i]*r3.y;
                    v0.z += am[3+i]*r6.z - am[6+i]*r3.z; v0.w += am[3+i]*r6.w - am[6+i]*r3.w;
                    v1.x += am[6+i]*r0.x - am[i]*r6.x;   v1.y += am[6+i]*r0.y - am[i]*r6.y;
                    v1.z += am[6+i]*r0.z - am[i]*r6.z;   v1.w += am[6+i]*r0.w - am[i]*r6.w;
                    v2.x += am[i]*r3.x - am[3+i]*r0.x;   v2.y += am[i]*r3.y - am[3+i]*r0.y;
                    v2.z += am[i]*r3.z - am[3+i]*r0.z;   v2.w += am[i]*r3.w - am[3+i]*r0.w;
                } } break;
            }
            const uint32_t base = pdst + (uint32_t)((zr * 3) * ROWB) + as_ * 128 + b0 * 2;
            st4(smemc, base, v0);
            st4(smemc, base + ROWB, v1);
            st4(smemc, base + 2 * ROWB, v2);
        }
    } else {
        for (int t = tid; t < 448; t += NTHR) {
            const int zr = t >> 5, r = t & 31;
            const int as_ = r >> 4, b0 = (r & 15) << 2;
            const int a = a0 + as_;
            const int z = (zr > nzv - 1) ? nzv - 1 : zr;
            const float* ax = smemf + z * 833;
            const __half* bz = smemh + z * X2H_STR;
            const float* av = ax + 64 + 3 * a;
            const float* am = ax + 256 + 9 * a;
            float4 v0;
            switch (p) {
            case 0: v0 = f4mul(ax[a], ld4h(bz + b0)); break;
            case 5: v0 = DOT3(ld4h(bz + 64 + b0), ld4h(bz + 128 + b0), ld4h(bz + 192 + b0),
                              av[0], av[1], av[2]); break;
            default: { // p13
                v0 = make_float4(0.f, 0.f, 0.f, 0.f);
#pragma unroll
                for (int t2 = 0; t2 < 9; t2++)
                    v0 = f4fma(am[t2], ld4h(bz + 256 + t2 * 64 + b0), v0);
            } break;
            }
            st4(smemc, pdst + (uint32_t)(zr * ROWB) + as_ * 128 + b0 * 2, v0);
        }
    }
}

__global__ void __launch_bounds__(NTHR, 1)
tp_hmma_kernel(const float* __restrict__ x1, const float* __restrict__ x2,
               float* __restrict__ out) {
    extern __shared__ char smem[];
    float* smemf = (float*)smem;
    __half* smemh = (__half*)(smem + X2H_OFF);
    const int tid = threadIdx.x, w = tid >> 5, lane = tid & 31;
    const int z0 = blockIdx.x * 14;
    const int nzv = min(14, 4096 - z0);
    const uint32_t sb = smem_u32(smem);
    const float SCL = 1.0f / 1024.0f;   // undo the W*1024 prescale

    // stage x1 (fp32, stride 833) and x2 (fp16 component-major, stride 848)
    for (int i = tid; i < 14 * 832; i += NTHR) {
        int z = i / 832, f = i - z * 832;
        int zg = z0 + z; if (zg > 4095) zg = 4095;
        smemf[z * 833 + f] = x1[(size_t)zg * 832 + f];
        float v2 = x2[(size_t)zg * 832 + f];
        int d;
        if (f < 64) d = f;
        else if (f < 256) { int g = f - 64; d = 64 + (g % 3) * 64 + g / 3; }
        else { int g = f - 256; d = 256 + (g % 9) * 64 + g / 9; }
        smemh[z * X2H_STR + d] = __float2half(v2);
    }

    // 16 warps. g2 (k-split): m-frag (w&7), k-half (w>>3), full n -> acc2[8][4]
    // g1: warps 0-11, m-frag (w%3), n16-slice (w/3), all k -> accX[2][4]
    // g0: warps 12-15, m-frag 0, n16-slice (w-12), all k   -> accX[2][4]
    float acc2[8][4], accX[2][4];
#pragma unroll
    for (int ni = 0; ni < 8; ni++)
#pragma unroll
        for (int di = 0; di < 4; di++) {
            acc2[ni][di] = 0.f;
            if (ni < 2) accX[ni][di] = 0.f;
        }

    // prologue: W0 in flight; stage visible; gen P0; wait; publish
    prefetch_w(0, 0, 0, sb, tid);
    asm volatile("cp.async.commit_group;" ::: "memory");
    __syncthreads();
    gen_chunk(0, c_grp[0], 0, nzv, smemf, smemh, smem, P_OFF, tid);
    asm volatile("cp.async.wait_group 0;" ::: "memory");
    __syncthreads();

    // invariant at top of iter c: P[c&1] + W[c&1] visible to all
    for (int c = 0; c < NCHUNK; c++) {
        const int cg = c + 1;
        if (cg < NCHUNK) {
            prefetch_w(cg >> 5, (cg & 31) * 2, cg & 1, sb, tid);
            asm volatile("cp.async.commit_group;" ::: "memory");
            gen_chunk(cg >> 5, c_grp[cg >> 5], (cg & 31) * 2, nzv, smemf, smemh, smem,
                      P_OFF + (cg & 1) * P_STRIDE, tid);
        }
        asm volatile("cp.async.wait_group 0;" ::: "memory");
        const int g = c_grp[c >> 5];
        const uint32_t pP = sb + P_OFF + (c & 1) * P_STRIDE;
        const uint32_t pW = sb + W_OFF + (c & 1) * W_STRIDE;
        if (g == 2) {
            warp_mma_g2(acc2, (w & 7) * 16, (w >> 3) * 4, pP, pW, lane);
        } else if (g == 1) {
            if (w < 12) warp_mma_x(accX, (w % 3) * 16, (w / 3) * 16, pP, pW, lane);
        } else {
            if (w >= 12) warp_mma_x(accX, 0, (w - 12) * 16, pP, pW, lane);
        }
        __syncthreads();   // publish P[(c+1)&1] and W[(c+1)&1]
    }

    // ---- epilogue ----
    // g2 k-split partial exchange through smem (reuse P stage 0: 128x64 fp32 = 32KB)
    float* xb = (float*)(smem + P_OFF);
    if (w >= 8) {
        const int mi = w & 7;
#pragma unroll
        for (int ni = 0; ni < 8; ni++)
#pragma unroll
            for (int di = 0; di < 4; di++) {
                int row = mi * 16 + (lane >> 2) + (di >> 1) * 8;
                int col = ni * 8 + (lane & 3) * 2 + (di & 1);
                xb[row * 64 + col] = acc2[ni][di];
            }
    }
    __syncthreads();
    if (w < 8) {
        const int mi = w;
#pragma unroll
        for (int ni = 0; ni < 8; ni++)
#pragma unroll
            for (int di = 0; di < 4; di++) {
                int row = mi * 16 + (lane >> 2) + (di >> 1) * 8;
                int col = ni * 8 + (lane & 3) * 2 + (di & 1);
                float v = acc2[ni][di] + xb[row * 64 + col];
                if (row < 126) {
                    int z = row / 9, u = row - z * 9;
                    if (z < nzv)
                        out[(size_t)(z0 + z) * 832 + 256 + col * 9 + u] = v * SCL;
                }
            }
    }
    // g1 / g0 outputs (D frag: row=(l>>2)+8*(di>>1), col=2*(l&3)+(di&1))
    if (w < 12) {
        const int m0 = (w % 3) * 16, n0 = (w / 3) * 16;
#pragma unroll
        for (int ni = 0; ni < 2; ni++)
#pragma unroll
            for (int di = 0; di < 4; di++) {
                int row = m0 + (lane >> 2) + (di >> 1) * 8;
                int col = n0 + ni * 8 + (lane & 3) * 2 + (di & 1);
                if (row < 42) {
                    int z = row / 3, u = row - z * 3;
                    if (z < nzv)
                        out[(size_t)(z0 + z) * 832 + 64 + col * 3 + u] = accX[ni][di] * SCL;
                }
            }
    } else {
        const int n0 = (w - 12) * 16;
#pragma unroll
        for (int ni = 0; ni < 2; ni++)
#pragma unroll
            for (int di = 0; di < 4; di++) {
                int row = (lane >> 2) + (di >> 1) * 8;
                int col = n0 + ni * 8 + (lane & 3) * 2 + (di & 1);
                if (row < nzv)
                    out[(size_t)(z0 + row) * 832 + col] = accX[ni][di] * SCL;
            }
    }
}

extern "C" void kernel_launch(void* const* d_in, const int* in_sizes, int n_in,
                              void* d_out, int out_size) {
    const float* x1 = (const float*)d_in[0];
    const float* x2 = (const float*)d_in[1];
    const float* w  = (const float*)d_in[2];
    float* out = (float*)d_out;

    prep_w<<<(WTE + 255) / 256, 256>>>(w);

    static int attr_set = 0;
    if (!attr_set) {
        cudaFuncSetAttribute(tp_hmma_kernel, cudaFuncAttributeMaxDynamicSharedMemorySize, SMEM_TOT);
        attr_set = 1;
    }
    tp_hmma_kernel<<<293, NTHR, SMEM_TOT>>>(x1, x2, out);
}